// round 16
// baseline (speedup 1.0000x reference)
#include <cuda_runtime.h>
#include <cuda_bf16.h>
#include <math.h>
#include <stdint.h>

// ---- problem constants ----
#define BB 8
#define LL 512
#define EE 256
#define HH 8
#define HD 32
#define BD_ 64
#define TD_ 256
#define TE_ 128
#define ED_ 64
#define MM_ 512
#define NROWS (BB*LL)          // 4096 token rows

typedef unsigned long long u64;

// ---- packed fp32x2 helpers ----
__device__ __forceinline__ u64 pk2(float x, float y) {
    u64 r; asm("mov.b64 %0,{%1,%2};" : "=l"(r) : "f"(x), "f"(y)); return r;
}
__device__ __forceinline__ void fma2(u64& d, u64 a, u64 b) {
    asm("fma.rn.f32x2 %0,%1,%2,%0;" : "+l"(d) : "l"(a), "l"(b));
}
__device__ __forceinline__ void unpk2(u64 v, float& x, float& y) {
    asm("mov.b64 {%0,%1},%2;" : "=f"(x), "=f"(y) : "l"(v));
}

// ---- HMMA / cp.async helpers (baseline PTX; valid on compute_103) ----
__device__ __forceinline__ uint32_t smem_u32(const void* p) {
    uint32_t a;
    asm("{ .reg .u64 t; cvta.to.shared.u64 t, %1; cvt.u32.u64 %0, t; }" : "=r"(a) : "l"(p));
    return a;
}
__device__ __forceinline__ void ldsm4(uint32_t& r0, uint32_t& r1, uint32_t& r2, uint32_t& r3,
                                      uint32_t addr) {
    asm volatile("ldmatrix.sync.aligned.m8n8.x4.shared.b16 {%0,%1,%2,%3},[%4];"
                 : "=r"(r0), "=r"(r1), "=r"(r2), "=r"(r3) : "r"(addr));
}
__device__ __forceinline__ void mma16816(float* d, const uint32_t* a, const uint32_t* b) {
    asm volatile(
        "mma.sync.aligned.m16n8k16.row.col.f32.bf16.bf16.f32 "
        "{%0,%1,%2,%3},{%4,%5,%6,%7},{%8,%9},{%0,%1,%2,%3};"
        : "+f"(d[0]), "+f"(d[1]), "+f"(d[2]), "+f"(d[3])
        : "r"(a[0]), "r"(a[1]), "r"(a[2]), "r"(a[3]), "r"(b[0]), "r"(b[1]));
}
__device__ __forceinline__ void cpasync16(uint32_t smaddr, const void* g) {
    asm volatile("cp.async.cg.shared.global [%0], [%1], 16;" :: "r"(smaddr), "l"(g));
}
#define CP_COMMIT() asm volatile("cp.async.commit_group;" ::: "memory")
#define CP_WAIT0()  asm volatile("cp.async.wait_group 0;" ::: "memory")
#define CP_WAIT1()  asm volatile("cp.async.wait_group 1;" ::: "memory")

// split fp32 -> bf16 hi + bf16 lo (residual), packed as bf16x2 pairs
__device__ __forceinline__ void split4(float4 v, uint2& hi, uint2& lo) {
    __nv_bfloat162 h01 = __float22bfloat162_rn(make_float2(v.x, v.y));
    __nv_bfloat162 h23 = __float22bfloat162_rn(make_float2(v.z, v.w));
    float2 f01 = __bfloat1622float2(h01);
    float2 f23 = __bfloat1622float2(h23);
    __nv_bfloat162 l01 = __float22bfloat162_rn(make_float2(v.x - f01.x, v.y - f01.y));
    __nv_bfloat162 l23 = __float22bfloat162_rn(make_float2(v.z - f23.x, v.w - f23.y));
    hi.x = *(uint32_t*)&h01; hi.y = *(uint32_t*)&h23;
    lo.x = *(uint32_t*)&l01; lo.y = *(uint32_t*)&l23;
}
__device__ __forceinline__ void packsplit(float x, float y, uint32_t& hi, uint32_t& lo) {
    __nv_bfloat162 h = __float22bfloat162_rn(make_float2(x, y));
    float2 f = __bfloat1622float2(h);
    __nv_bfloat162 l = __float22bfloat162_rn(make_float2(x - f.x, y - f.y));
    hi = *(uint32_t*)&h; lo = *(uint32_t*)&l;
}

// ---- scratch ----
__device__ float g_u[NROWS*TD_];
__device__ float g_m[NROWS*6*EE];
__device__ float g_x[NROWS*EE];
__device__ float g_bias[(size_t)BB*HH*LL*LL];
__device__ float g_qkv[NROWS*3*EE];
__device__ float g_o[NROWS*EE];
__device__ float g_h1[NROWS*EE];
__device__ float g_t1[NROWS*MM_];
__device__ float g_h2[NROWS*EE];
__device__ float g_tt[NROWS*EE];   // s_tem @ W_tem^T + b_tem
__device__ float g_ti[NROWS*EE];   // h_init @ W_init^T + b_init

#define EPI_BIAS     0
#define EPI_SILU     1
#define EPI_GATE_RES 2
#define EPI_ADD_SILU 4

// =====================================================================
// GEMM epilogue (shared)
// =====================================================================
template<int EPI>
__device__ __forceinline__ void gemm_epilogue(
    float acc[2][4][4], int bm, int bn, int wm, int wn, int lane,
    float* __restrict__ C, int Nd, const float* __restrict__ bias,
    const float* __restrict__ gate, int goff, const float* __restrict__ res)
{
    int g = lane >> 2, tig = lane & 3;
    #pragma unroll
    for (int mi = 0; mi < 2; mi++) {
        #pragma unroll
        for (int ni = 0; ni < 4; ni++) {
            int n0 = bn + wn + ni*8 + tig*2;
            float2 b2 = *(const float2*)&bias[n0];
            #pragma unroll
            for (int rh = 0; rh < 2; rh++) {
                int m = bm + wm + mi*16 + g + rh*8;
                float x0 = acc[mi][ni][rh*2 + 0] + b2.x;
                float x1 = acc[mi][ni][rh*2 + 1] + b2.y;
                if (EPI == EPI_SILU) {
                    x0 = x0 / (1.f + __expf(-x0));
                    x1 = x1 / (1.f + __expf(-x1));
                }
                if (EPI == EPI_GATE_RES) {
                    float2 g2 = *(const float2*)&gate[(size_t)m*(6*EE) + goff + n0];
                    float2 r2 = *(const float2*)&res[(size_t)m*Nd + n0];
                    x0 = x0*g2.x + r2.x;
                    x1 = x1*g2.y + r2.y;
                }
                if (EPI == EPI_ADD_SILU) {
                    float2 r2 = *(const float2*)&res[(size_t)m*Nd + n0];
                    x0 += r2.x; x1 += r2.y;
                    x0 = x0 / (1.f + __expf(-x0));
                    x1 = x1 / (1.f + __expf(-x1));
                }
                *(float2*)&C[(size_t)m*Nd + n0] = make_float2(x0, x1);
            }
        }
    }
}

// =====================================================================
// cp.async-pipelined HMMA GEMM body (96KB)
// =====================================================================
#define OFF_AHI 0
#define OFF_ALO 16384
#define OFF_BHI 32768
#define OFF_BLO 40960
#define OFF_F32A 49152
#define OFF_F32B (49152 + 32768)
#define GEMM_SMEM_PIPE (49152 + 49152)

template<int EPI>
__device__ __forceinline__ void hmma_gemm_pipe(
    char* sm, int bm, int bn,
    const float* __restrict__ A, const float* __restrict__ B, float* __restrict__ C,
    int Nd, int Kd,
    const float* __restrict__ bias,
    const float* __restrict__ gate, int goff,
    const float* __restrict__ res)
{
    uint32_t sb = smem_u32(sm);
    int tid = threadIdx.x, wid = tid >> 5, lane = tid & 31;
    int wm = (wid & 3)*32, wn = (wid >> 2)*32;

    float acc[2][4][4];
    #pragma unroll
    for (int mi = 0; mi < 2; mi++)
        #pragma unroll
        for (int ni = 0; ni < 4; ni++)
            #pragma unroll
            for (int c = 0; c < 4; c++) acc[mi][ni][c] = 0.f;

    int arow = (lane & 15), acol = (lane >> 4);
    int brow = (lane & 7) + ((lane >> 4) << 3), bcol = (lane >> 3) & 1;

    int nch = Kd >> 6;
    {
        const float* Ab = A + (size_t)bm*Kd;
        const float* Bb = B + (size_t)bn*Kd;
        #pragma unroll
        for (int i = 0; i < 8; i++) {
            int idx = tid + i*256;
            int r = idx >> 4, c4 = idx & 15;
            cpasync16(sb + OFF_F32A + idx*16, Ab + (size_t)r*Kd + c4*4);
        }
        #pragma unroll
        for (int i = 0; i < 4; i++) {
            int idx = tid + i*256;
            int r = idx >> 4, c4 = idx & 15;
            cpasync16(sb + OFF_F32B + idx*16, Bb + (size_t)r*Kd + c4*4);
        }
        CP_COMMIT();
    }

    for (int ch = 0; ch < nch; ch++) {
        CP_WAIT0();
        __syncthreads();
        #pragma unroll
        for (int i = 0; i < 8; i++) {
            int idx = tid + i*256;
            int r = idx >> 4, c4 = idx & 15;
            float4 v = *(const float4*)(sm + OFF_F32A + idx*16);
            uint2 hi, lo; split4(v, hi, lo);
            uint32_t off = (uint32_t)(r*128 + c4*8);
            uint32_t sw = off ^ (((uint32_t)(r & 7)) << 4);
            *(uint2*)(sm + OFF_AHI + sw) = hi;
            *(uint2*)(sm + OFF_ALO + sw) = lo;
        }
        #pragma unroll
        for (int i = 0; i < 4; i++) {
            int idx = tid + i*256;
            int r = idx >> 4, c4 = idx & 15;
            float4 v = *(const float4*)(sm + OFF_F32B + idx*16);
            uint2 hi, lo; split4(v, hi, lo);
            uint32_t off = (uint32_t)(r*128 + c4*8);
            uint32_t sw = off ^ (((uint32_t)(r & 7)) << 4);
            *(uint2*)(sm + OFF_BHI + sw) = hi;
            *(uint2*)(sm + OFF_BLO + sw) = lo;
        }
        __syncthreads();

        if (ch + 1 < nch) {
            const float* Ab = A + (size_t)bm*Kd + (ch + 1)*64;
            const float* Bb = B + (size_t)bn*Kd + (ch + 1)*64;
            #pragma unroll
            for (int i = 0; i < 8; i++) {
                int idx = tid + i*256;
                int r = idx >> 4, c4 = idx & 15;
                cpasync16(sb + OFF_F32A + idx*16, Ab + (size_t)r*Kd + c4*4);
            }
            #pragma unroll
            for (int i = 0; i < 4; i++) {
                int idx = tid + i*256;
                int r = idx >> 4, c4 = idx & 15;
                cpasync16(sb + OFF_F32B + idx*16, Bb + (size_t)r*Kd + c4*4);
            }
            CP_COMMIT();
        }

        #pragma unroll
        for (int ks = 0; ks < 4; ks++) {
            uint32_t ah[2][4], al[2][4], bh[2][4], bl[2][4];
            #pragma unroll
            for (int mi = 0; mi < 2; mi++) {
                int row = wm + mi*16 + arow;
                uint32_t off = (uint32_t)(row*128 + (ks*2 + acol)*16);
                uint32_t sw = off ^ (((uint32_t)(row & 7)) << 4);
                ldsm4(ah[mi][0], ah[mi][1], ah[mi][2], ah[mi][3], sb + OFF_AHI + sw);
                ldsm4(al[mi][0], al[mi][1], al[mi][2], al[mi][3], sb + OFF_ALO + sw);
            }
            #pragma unroll
            for (int nh = 0; nh < 2; nh++) {
                int row = wn + nh*16 + brow;
                uint32_t off = (uint32_t)(row*128 + (ks*2 + bcol)*16);
                uint32_t sw = off ^ (((uint32_t)(row & 7)) << 4);
                ldsm4(bh[nh][0], bh[nh][1], bh[nh][2], bh[nh][3], sb + OFF_BHI + sw);
                ldsm4(bl[nh][0], bl[nh][1], bl[nh][2], bl[nh][3], sb + OFF_BLO + sw);
            }
            #pragma unroll
            for (int mi = 0; mi < 2; mi++)
                #pragma unroll
                for (int ni = 0; ni < 4; ni++) {
                    const uint32_t* bph = &bh[ni >> 1][(ni & 1)*2];
                    const uint32_t* bpl = &bl[ni >> 1][(ni & 1)*2];
                    mma16816(acc[mi][ni], ah[mi], bph);
                    mma16816(acc[mi][ni], ah[mi], bpl);
                    mma16816(acc[mi][ni], al[mi], bph);
                }
        }
    }
    gemm_epilogue<EPI>(acc, bm, bn, wm, wn, lane, C, Nd, bias, gate, goff, res);
}

template<int EPI>
__global__ void __launch_bounds__(256) k_gemmH(
    const float* __restrict__ A, const float* __restrict__ B, float* __restrict__ C,
    int Nd, int Kd,
    const float* __restrict__ bias,
    const float* __restrict__ gate, int goff,
    const float* __restrict__ res)
{
    extern __shared__ char smh[];
    hmma_gemm_pipe<EPI>(smh, blockIdx.y*128, blockIdx.x*64, A, B, C, Nd, Kd, bias, gate, goff, res);
}

// =====================================================================
// bias body — cp.async double-buffered (unchanged)
// =====================================================================
__device__ __forceinline__ void bias_body(
        float* sm, int blk,
        const float* __restrict__ p, const float* __restrict__ g_eln,
        const float* __restrict__ b_eln, const float* __restrict__ W_e,
        const float* __restrict__ b_e)
{
    float* sW   = sm + 2*128*64;
    float* scs  = sW + 512;
    float* sct  = scs + 8;
    int tid = threadIdx.x;
    uint32_t sb = smem_u32(sm);

    for (int i = tid; i < 512; i += 256) sW[i] = g_eln[i & 63]*W_e[i];
    if (tid < 8) {
        float ct = 0.f;
        for (int k = 0; k < 64; k++) ct += b_eln[k]*W_e[tid*64 + k];
        sct[tid] = ct + b_e[tid];
    }
    __syncthreads();
    if (tid < 8) {
        float cs = 0.f;
        for (int k = 0; k < 64; k++) cs += sW[tid*64 + k];
        scs[tid] = cs;
    }

    int b = blk >> 9, l = blk & 511;
    const char* src = (const char*)(p + (size_t)blk*512*64);
    u64 one2 = pk2(1.f, 1.f);

    #pragma unroll
    for (int j = 0; j < 8; j++) {
        int idx = j*256 + tid;
        int r = idx >> 4, c = idx & 15;
        cpasync16(sb + (uint32_t)((r*64 + ((c ^ (r & 15)) << 2))*4), src + (size_t)idx*16);
    }
    CP_COMMIT();

    for (int ch = 0; ch < 4; ch++) {
        if (ch < 3) {
            uint32_t dstb = sb + (uint32_t)(((ch + 1) & 1)*32768);
            const char* s2 = src + (size_t)(ch + 1)*128*64*4;
            #pragma unroll
            for (int j = 0; j < 8; j++) {
                int idx = j*256 + tid;
                int r = idx >> 4, c = idx & 15;
                cpasync16(dstb + (uint32_t)((r*64 + ((c ^ (r & 15)) << 2))*4), s2 + (size_t)idx*16);
            }
            CP_COMMIT();
            CP_WAIT1();
        } else {
            CP_WAIT0();
        }
        __syncthreads();

        if (tid < 128) {
            const float* base = sm + (ch & 1)*8192 + tid*64;
            int swz = tid & 15;
            u64 P2[8] = {};
            u64 s2v = 0, q2 = 0;
            #pragma unroll
            for (int c = 0; c < 16; c++) {
                float4 a4 = *(const float4*)&base[(c ^ swz) << 2];
                u64 a01 = ((const u64*)&a4)[0];
                u64 a23 = ((const u64*)&a4)[1];
                fma2(s2v, a01, one2); fma2(s2v, a23, one2);
                fma2(q2, a01, a01);   fma2(q2, a23, a23);
                #pragma unroll
                for (int hh = 0; hh < 8; hh++) {
                    float4 w4 = *(const float4*)&sW[hh*64 + c*4];
                    fma2(P2[hh], a01, ((const u64*)&w4)[0]);
                    fma2(P2[hh], a23, ((const u64*)&w4)[1]);
                }
            }
            float sx, sy, qx, qy;
            unpk2(s2v, sx, sy); unpk2(q2, qx, qy);
            float s = sx + sy, q = qx + qy;
            float mu = s*(1.f/64.f);
            float var = q*(1.f/64.f) - mu*mu;
            float rstd = rsqrtf(var + 1e-5f);
            int m = ch*128 + tid;
            #pragma unroll
            for (int hh = 0; hh < 8; hh++) {
                float px, py;
                unpk2(P2[hh], px, py);
                g_bias[(((size_t)b*HH + hh)*LL + l)*LL + m] = rstd*((px + py) - mu*scs[hh]) + sct[hh];
            }
        }
        __syncthreads();
    }
}

// =====================================================================
// FAT kernel: up to 3 GEMM ranges (range1 templated EPI, others EPI_BIAS)
// + bias blocks, one launch. 96KB dynamic smem covers all bodies.
// =====================================================================
template<int EPI>
__global__ void __launch_bounds__(256) k_fat3(
    int nTX1, int nB1,
    const float* __restrict__ A1, const float* __restrict__ B1c, float* __restrict__ C1,
    int Nd1, int Kd1, const float* __restrict__ bias1, const float* __restrict__ res1,
    int nTX2, int nB2,
    const float* __restrict__ A2, const float* __restrict__ B2c, float* __restrict__ C2,
    int Nd2, int Kd2, const float* __restrict__ bias2,
    int nTX3, int nB3,
    const float* __restrict__ A3, const float* __restrict__ B3c, float* __restrict__ C3,
    int Nd3, int Kd3, const float* __restrict__ bias3,
    const float* __restrict__ p, const float* __restrict__ g_eln,
    const float* __restrict__ b_eln, const float* __restrict__ W_e,
    const float* __restrict__ b_e, int biasOffset)
{
    extern __shared__ char smf[];
    int bid = blockIdx.x;
    if (bid < nB1) {
        hmma_gemm_pipe<EPI>(smf, (bid/nTX1)*128, (bid % nTX1)*64,
                            A1, B1c, C1, Nd1, Kd1, bias1, nullptr, 0, res1);
    } else if (bid < nB1 + nB2) {
        int b2 = bid - nB1;
        hmma_gemm_pipe<EPI_BIAS>(smf, (b2/nTX2)*128, (b2 % nTX2)*64,
                                 A2, B2c, C2, Nd2, Kd2, bias2, nullptr, 0, nullptr);
    } else if (bid < nB1 + nB2 + nB3) {
        int b3 = bid - nB1 - nB2;
        hmma_gemm_pipe<EPI_BIAS>(smf, (b3/nTX3)*128, (b3 % nTX3)*64,
                                 A3, B3c, C3, Nd3, Kd3, bias3, nullptr, 0, nullptr);
    } else {
        bias_body((float*)smf, biasOffset + bid - nB1 - nB2 - nB3,
                  p, g_eln, b_eln, W_e, b_e);
    }
}

// =====================================================================
// k_xmod / k_dual_ln — float4, 4 rows per 256-thread block
// =====================================================================
__global__ void k_xmod(const float* __restrict__ src, int sh_off, int sc_off,
                       float* __restrict__ dst)
{
    int tid = threadIdx.x;
    int rl = tid >> 6, sub = tid & 63;
    int row = blockIdx.x*4 + rl;
    size_t base = (size_t)row*EE + sub*4;
    float4 v = *(const float4*)&src[base];
    float a = v.x + v.y + v.z + v.w;
    float b = v.x*v.x + v.y*v.y + v.z*v.z + v.w*v.w;
    #pragma unroll
    for (int o = 16; o > 0; o >>= 1) {
        a += __shfl_xor_sync(0xffffffffu, a, o);
        b += __shfl_xor_sync(0xffffffffu, b, o);
    }
    __shared__ float s1[8], s2[8];
    int wid = tid >> 5;
    if ((tid & 31) == 0) { s1[wid] = a; s2[wid] = b; }
    __syncthreads();
    float suma = s1[rl*2] + s1[rl*2 + 1];
    float sumb = s2[rl*2] + s2[rl*2 + 1];
    float mu = suma*(1.f/EE);
    float var = sumb*(1.f/EE) - mu*mu;
    float rstd = rsqrtf(var + 1e-5f);
    const float* mrow = g_m + (size_t)row*(6*EE);
    float4 sc4 = *(const float4*)&mrow[sc_off + sub*4];
    float4 sh4 = *(const float4*)&mrow[sh_off + sub*4];
    float4 o4;
    o4.x = (v.x - mu)*rstd*(1.f + sc4.x) + sh4.x;
    o4.y = (v.y - mu)*rstd*(1.f + sc4.y) + sh4.y;
    o4.z = (v.z - mu)*rstd*(1.f + sc4.z) + sh4.z;
    o4.w = (v.w - mu)*rstd*(1.f + sc4.w) + sh4.w;
    *(float4*)&dst[base] = o4;
}

__global__ void k_dual_ln(const float* __restrict__ a_, const float* __restrict__ b_,
                          const float* __restrict__ g1, const float* __restrict__ bt1,
                          const float* __restrict__ c_,
                          const float* __restrict__ g2, const float* __restrict__ bt2,
                          float* __restrict__ dst)
{
    int tid = threadIdx.x;
    int rl = tid >> 6, sub = tid & 63;
    int row = blockIdx.x*4 + rl;
    size_t base = (size_t)row*EE + sub*4;
    __shared__ float s1[8], s2[8];
    int wid = tid >> 5;

    float4 va = *(const float4*)&a_[base];
    float4 vb = *(const float4*)&b_[base];
    float4 v;
    v.x = va.x + vb.x; v.y = va.y + vb.y; v.z = va.z + vb.z; v.w = va.w + vb.w;
    float a = v.x + v.y + v.z + v.w;
    float b = v.x*v.x + v.y*v.y + v.z*v.z + v.w*v.w;
    #pragma unroll
    for (int o = 16; o > 0; o >>= 1) {
        a += __shfl_xor_sync(0xffffffffu, a, o);
        b += __shfl_xor_sync(0xffffffffu, b, o);
    }
    if ((tid & 31) == 0) { s1[wid] = a; s2[wid] = b; }
    __syncthreads();
    float mu = (s1[rl*2] + s1[rl*2+1])*(1.f/EE);
    float var = (s2[rl*2] + s2[rl*2+1])*(1.f/EE) - mu*mu;
    float rstd = rsqrtf(var + 1e-5f);
    float4 gg = *(const float4*)&g1[sub*4];
    float4 bb = *(const float4*)&bt1[sub*4];
    float4 x1;
    x1.x = (v.x - mu)*rstd*gg.x + bb.x;
    x1.y = (v.y - mu)*rstd*gg.y + bb.y;
    x1.z = (v.z - mu)*rstd*gg.z + bb.z;
    x1.w = (v.w - mu)*rstd*gg.w + bb.w;

    float4 vc = *(const float4*)&c_[base];
    float4 v2;
    v2.x = x1.x + vc.x; v2.y = x1.y + vc.y; v2.z = x1.z + vc.z; v2.w = x1.w + vc.w;
    a = v2.x + v2.y + v2.z + v2.w;
    b = v2.x*v2.x + v2.y*v2.y + v2.z*v2.z + v2.w*v2.w;
    #pragma unroll
    for (int o = 16; o > 0; o >>= 1) {
        a += __shfl_xor_sync(0xffffffffu, a, o);
        b += __shfl_xor_sync(0xffffffffu, b, o);
    }
    __syncthreads();    // s1/s2 reuse
    if ((tid & 31) == 0) { s1[wid] = a; s2[wid] = b; }
    __syncthreads();
    mu = (s1[rl*2] + s1[rl*2+1])*(1.f/EE);
    var = (s2[rl*2] + s2[rl*2+1])*(1.f/EE) - mu*mu;
    rstd = rsqrtf(var + 1e-5f);
    gg = *(const float4*)&g2[sub*4];
    bb = *(const float4*)&bt2[sub*4];
    float4 o4;
    o4.x = (v2.x - mu)*rstd*gg.x + bb.x;
    o4.y = (v2.y - mu)*rstd*gg.y + bb.y;
    o4.z = (v2.z - mu)*rstd*gg.z + bb.z;
    o4.w = (v2.w - mu)*rstd*gg.w + bb.w;
    *(float4*)&dst[base] = o4;
}

// =====================================================================
// k_attnH — HMMA flash attention + cp.async bias prefetch (unchanged)
// =====================================================================
#define AOFF_QH 0
#define AOFF_QL 4096
#define AOFF_KH 8192
#define AOFF_KL 12288
#define AOFF_VH 16384
#define AOFF_VL 24576
#define AOFF_B  32768
#define ATTN_SMEM 65536

__global__ void __launch_bounds__(128) k_attnH()
{
    extern __shared__ char sma[];
    char* sQh = sma + AOFF_QH;  char* sQl = sma + AOFF_QL;
    char* sKh = sma + AOFF_KH;  char* sKl = sma + AOFF_KL;
    char* sVh = sma + AOFF_VH;  char* sVl = sma + AOFF_VL;
    uint32_t sb = smem_u32(sma);

    int tid = threadIdx.x, lane = tid & 31, wid = tid >> 5;
    int bh = blockIdx.y;
    int b = bh >> 3, h = bh & 7;
    int l0 = blockIdx.x*64;
    int wm = wid*16;
    int g = lane >> 2, tig = lane & 3;

    #pragma unroll
    for (int i = 0; i < 4; i++) {
        int idx = tid + i*128;
        int r = idx >> 3, c4 = idx & 7;
        float4 v = *(const float4*)(g_qkv + (size_t)(b*LL + l0 + r)*768 + h*HD + c4*4);
        uint2 hi, lo; split4(v, hi, lo);
        int chunk = c4 >> 1, half = c4 & 1;
        int cs = chunk ^ ((r >> 1) & 3);
        int addr = r*64 + cs*16 + half*8;
        *(uint2*)(sQh + addr) = hi;
        *(uint2*)(sQl + addr) = lo;
    }
    const char* bsrc = (const char*)(g_bias + (((size_t)(b*HH + h)*LL + l0))*LL);
    #pragma unroll
    for (int j = 0; j < 8; j++) {
        int idx = j*128 + tid;
        int r = idx >> 4, c = idx & 15;
        cpasync16(sb + AOFF_B + (uint32_t)(r*256 + ((c ^ (r & 15)) << 4)),
                  bsrc + (size_t)r*2048 + c*16);
    }
    CP_COMMIT();
    __syncthreads();

    uint32_t qh[2][4], ql[2][4];
    {
        int arow = lane & 15, acol = lane >> 4;
        int row = wm + arow;
        #pragma unroll
        for (int kt = 0; kt < 2; kt++) {
            int c = kt*2 + acol;
            int cs = c ^ ((row >> 1) & 3);
            uint32_t off = (uint32_t)(row*64 + cs*16);
            ldsm4(qh[kt][0], qh[kt][1], qh[kt][2], qh[kt][3], sb + AOFF_QH + off);
            ldsm4(ql[kt][0], ql[kt][1], ql[kt][2], ql[kt][3], sb + AOFF_QL + off);
        }
    }

    float of[4][4];
    #pragma unroll
    for (int nt = 0; nt < 4; nt++)
        #pragma unroll
        for (int c = 0; c < 4; c++) of[nt][c] = 0.f;
    float m_run[2] = {-1e30f, -1e30f};
    float l_run[2] = {0.f, 0.f};

    int brow = (lane & 7) + ((lane >> 4) << 3);
    int bcol = (lane >> 3) & 1;
    const float sc = 0.17677669529663687f;

    for (int ch = 0; ch < 8; ch++) {
        int m0 = ch*64;
        __syncthreads();
        #pragma unroll
        for (int i = 0; i < 4; i++) {
            int idx = tid + i*128;
            int r = idx >> 3, c4 = idx & 7;
            float4 v = *(const float4*)(g_qkv + (size_t)(b*LL + m0 + r)*768 + 256 + h*HD + c4*4);
            uint2 hi, lo; split4(v, hi, lo);
            int chunk = c4 >> 1, half = c4 & 1;
            int cs = chunk ^ ((r >> 1) & 3);
            int addr = r*64 + cs*16 + half*8;
            *(uint2*)(sKh + addr) = hi;
            *(uint2*)(sKl + addr) = lo;
        }
        #pragma unroll
        for (int i = 0; i < 4; i++) {
            int idx = tid + i*128;
            int m = idx >> 3, c4 = idx & 7;
            float4 v = *(const float4*)(g_qkv + (size_t)(b*LL + m0 + m)*768 + 512 + h*HD + c4*4);
            float vf[4] = {v.x, v.y, v.z, v.w};
            #pragma unroll
            for (int j = 0; j < 4; j++) {
                int hd = c4*4 + j;
                __nv_bfloat16 hb = __float2bfloat16_rn(vf[j]);
                __nv_bfloat16 lb = __float2bfloat16_rn(vf[j] - __bfloat162float(hb));
                int cs = (m >> 3) ^ (hd & 7);
                int addr = hd*128 + cs*16 + (m & 7)*2;
                *(__nv_bfloat16*)(sVh + addr) = hb;
                *(__nv_bfloat16*)(sVl + addr) = lb;
            }
        }
        if (ch < 7) {
            uint32_t dstb = sb + AOFF_B + (uint32_t)(((ch + 1) & 1)*16384);
            const char* b2 = bsrc + (size_t)(ch + 1)*64*4;
            #pragma unroll
            for (int j = 0; j < 8; j++) {
                int idx = j*128 + tid;
                int r = idx >> 4, c = idx & 15;
                cpasync16(dstb + (uint32_t)(r*256 + ((c ^ (r & 15)) << 4)),
                          b2 + (size_t)r*2048 + c*16);
            }
            CP_COMMIT();
        }
        __syncthreads();

        float s[8][4];
        #pragma unroll
        for (int nt = 0; nt < 8; nt++)
            #pragma unroll
            for (int c = 0; c < 4; c++) s[nt][c] = 0.f;
        #pragma unroll
        for (int ng = 0; ng < 4; ng++) {
            int row = ng*16 + brow;
            #pragma unroll
            for (int kt = 0; kt < 2; kt++) {
                int c = kt*2 + bcol;
                int cs = c ^ ((row >> 1) & 3);
                uint32_t off = (uint32_t)(row*64 + cs*16);
                uint32_t kh[4], kl[4];
                ldsm4(kh[0], kh[1], kh[2], kh[3], sb + AOFF_KH + off);
                ldsm4(kl[0], kl[1], kl[2], kl[3], sb + AOFF_KL + off);
                mma16816(s[2*ng],   qh[kt], &kh[0]);
                mma16816(s[2*ng+1], qh[kt], &kh[2]);
                mma16816(s[2*ng],   qh[kt], &kl[0]);
                mma16816(s[2*ng+1], qh[kt], &kl[2]);
                mma16816(s[2*ng],   ql[kt], &kh[0]);
                mma16816(s[2*ng+1], ql[kt], &kh[2]);
            }
        }

        if (ch < 7) { CP_WAIT1(); } else { CP_WAIT0(); }
        __syncthreads();
        {
            const char* bp = sma + AOFF_B + (ch & 1)*16384;
            int r0 = wm + g, r1 = wm + g + 8;
            int half8 = (tig & 1)*8;
            #pragma unroll
            for (int nt = 0; nt < 8; nt++) {
                int cg = 2*nt + (tig >> 1);
                float2 b0 = *(const float2*)(bp + r0*256 + ((cg ^ (r0 & 15)) << 4) + half8);
                float2 b1 = *(const float2*)(bp + r1*256 + ((cg ^ (r1 & 15)) << 4) + half8);
                s[nt][0] = s[nt][0]*sc + b0.x;
                s[nt][1] = s[nt][1]*sc + b0.y;
                s[nt][2] = s[nt][2]*sc + b1.x;
                s[nt][3] = s[nt][3]*sc + b1.y;
            }
        }

        #pragma unroll
        for (int hf = 0; hf < 2; hf++) {
            int c0 = hf*2;
            float rm = -1e30f;
            #pragma unroll
            for (int nt = 0; nt < 8; nt++)
                rm = fmaxf(rm, fmaxf(s[nt][c0], s[nt][c0+1]));
            rm = fmaxf(rm, __shfl_xor_sync(0xffffffffu, rm, 1));
            rm = fmaxf(rm, __shfl_xor_sync(0xffffffffu, rm, 2));
            float mnew = fmaxf(m_run[hf], rm);
            float f = __expf(m_run[hf] - mnew);
            float rs = 0.f;
            #pragma unroll
            for (int nt = 0; nt < 8; nt++) {
                float p0 = __expf(s[nt][c0]   - mnew);
                float p1 = __expf(s[nt][c0+1] - mnew);
                s[nt][c0] = p0; s[nt][c0+1] = p1;
                rs += p0 + p1;
            }
            rs += __shfl_xor_sync(0xffffffffu, rs, 1);
            rs += __shfl_xor_sync(0xffffffffu, rs, 2);
            l_run[hf] = l_run[hf]*f + rs;
            m_run[hf] = mnew;
            #pragma unroll
            for (int nt = 0; nt < 4; nt++) { of[nt][c0] *= f; of[nt][c0+1] *= f; }
        }

        #pragma unroll
        for (int jp = 0; jp < 4; jp++) {
            uint32_t ah[4], al[4];
            packsplit(s[2*jp][0],   s[2*jp][1],   ah[0], al[0]);
            packsplit(s[2*jp][2],   s[2*jp][3],   ah[1], al[1]);
            packsplit(s[2*jp+1][0], s[2*jp+1][1], ah[2], al[2]);
            packsplit(s[2*jp+1][2], s[2*jp+1][3], ah[3], al[3]);
            uint32_t vh[2][4], vl[2][4];
            #pragma unroll
            for (int nh = 0; nh < 2; nh++) {
                int row = nh*16 + brow;
                int c = jp*2 + bcol;
                int cs = c ^ (row & 7);
                uint32_t off = (uint32_t)(row*128 + cs*16);
                ldsm4(vh[nh][0], vh[nh][1], vh[nh][2], vh[nh][3], sb + AOFF_VH + off);
                ldsm4(vl[nh][0], vl[nh][1], vl[nh][2], vl[nh][3], sb + AOFF_VL + off);
            }
            #pragma unroll
            for (int nt = 0; nt < 4; nt++) {
                const uint32_t* bph = &vh[nt >> 1][(nt & 1)*2];
                const uint32_t* bpl = &vl[nt >> 1][(nt & 1)*2];
                mma16816(of[nt], ah, bph);
                mma16816(of[nt], ah, bpl);
                mma16816(of[nt], al, bph);
            }
        }
    }

    float inv0 = 1.f/l_run[0], inv1 = 1.f/l_run[1];
    #pragma unroll
    for (int nt = 0; nt < 4; nt++) {
        int col = h*HD + nt*8 + tig*2;
        int r0 = b*LL + l0 + wm + g;
        *(float2*)&g_o[(size_t)r0*EE + col] =
            make_float2(of[nt][0]*inv0, of[nt][1]*inv0);
        *(float2*)&g_o[(size_t)(r0 + 8)*EE + col] =
            make_float2(of[nt][2]*inv1, of[nt][3]*inv1);
    }
}

// =====================================================================
// launch — single stream; bias distributed over three fat front launches
// =====================================================================
extern "C" void kernel_launch(void* const* d_in, const int* in_sizes, int n_in,
                              void* d_out, int out_size)
{
    const float* h      = (const float*)d_in[0];
    const float* h_init = (const float*)d_in[1];
    const float* s_a    = (const float*)d_in[2];
    const float* s_t    = (const float*)d_in[3];
    const float* s_tem  = (const float*)d_in[4];
    const float* p      = (const float*)d_in[5];
    const float* W_bp   = (const float*)d_in[6];
    const float* b_bp   = (const float*)d_in[7];
    const float* W_ada  = (const float*)d_in[8];
    const float* b_ada  = (const float*)d_in[9];
    const float* g_eln  = (const float*)d_in[10];
    const float* b_eln  = (const float*)d_in[11];
    const float* W_e    = (const float*)d_in[12];
    const float* b_e    = (const float*)d_in[13];
    const float* W_in   = (const float*)d_in[14];
    const float* b_in   = (const float*)d_in[15];
    const float* W_out  = (const float*)d_in[16];
    const float* b_out  = (const float*)d_in[17];
    const float* W1     = (const float*)d_in[18];
    const float* b1     = (const float*)d_in[19];
    const float* W2     = (const float*)d_in[20];
    const float* b2     = (const float*)d_in[21];
    const float* W_tem  = (const float*)d_in[22];
    const float* b_tem  = (const float*)d_in[23];
    const float* g_tem  = (const float*)d_in[24];
    const float* bt_tem = (const float*)d_in[25];
    const float* W_init = (const float*)d_in[26];
    const float* b_init = (const float*)d_in[27];
    const float* g_init = (const float*)d_in[28];
    const float* bt_init= (const float*)d_in[29];
    float* out = (float*)d_out;

    float *pu, *pm, *px, *pqkv, *po, *ph1, *pt1, *ph2, *ptt, *pti;
    cudaGetSymbolAddress((void**)&pu,   g_u);
    cudaGetSymbolAddress((void**)&pm,   g_m);
    cudaGetSymbolAddress((void**)&px,   g_x);
    cudaGetSymbolAddress((void**)&pqkv, g_qkv);
    cudaGetSymbolAddress((void**)&po,   g_o);
    cudaGetSymbolAddress((void**)&ph1,  g_h1);
    cudaGetSymbolAddress((void**)&pt1,  g_t1);
    cudaGetSymbolAddress((void**)&ph2,  g_h2);
    cudaGetSymbolAddress((void**)&ptt,  g_tt);
    cudaGetSymbolAddress((void**)&pti,  g_ti);

    cudaFuncSetAttribute(k_fat3<EPI_ADD_SILU>, cudaFuncAttributeMaxDynamicSharedMemorySize, GEMM_SMEM_PIPE);
    cudaFuncSetAttribute(k_fat3<EPI_BIAS>,     cudaFuncAttributeMaxDynamicSharedMemorySize, GEMM_SMEM_PIPE);
    cudaFuncSetAttribute(k_gemmH<EPI_BIAS>,     cudaFuncAttributeMaxDynamicSharedMemorySize, GEMM_SMEM_PIPE);
    cudaFuncSetAttribute(k_gemmH<EPI_SILU>,     cudaFuncAttributeMaxDynamicSharedMemorySize, GEMM_SMEM_PIPE);
    cudaFuncSetAttribute(k_gemmH<EPI_GATE_RES>, cudaFuncAttributeMaxDynamicSharedMemorySize, GEMM_SMEM_PIPE);
    cudaFuncSetAttribute(k_attnH, cudaFuncAttributeMaxDynamicSharedMemorySize, ATTN_SMEM);

    const int B1 = 1200, B2 = 1800, B3 = 4096 - B1 - B2;

    // fatA: cond1(128, EPI_ADD_SILU) + Winit(128) + Wtem(128) + bias part 1
    k_fat3<EPI_ADD_SILU><<<384 + B1, 256, GEMM_SMEM_PIPE>>>(
        4, 128, s_a, W_bp, pu, TD_, BD_, b_bp, s_t,
        4, 128, h_init, W_init, pti, EE, EE, b_init,
        4, 128, s_tem, W_tem, ptt, EE, TE_, b_tem,
        p, g_eln, b_eln, W_e, b_e, 0);

    // fatB: ada(768) + bias part 2
    k_fat3<EPI_BIAS><<<768 + B2, 256, GEMM_SMEM_PIPE>>>(
        24, 768, pu, W_ada, pm, 6*EE, TD_, b_ada, nullptr,
        0, 0, nullptr, nullptr, nullptr, 0, 64, nullptr,
        0, 0, nullptr, nullptr, nullptr, 0, 64, nullptr,
        p, g_eln, b_eln, W_e, b_e, B1);

    // xmod (needs g_m from fatB)
    k_xmod<<<NROWS/4, 256>>>(h, 0, EE, px);

    // fatC: qkv(384) + bias part 3
    k_fat3<EPI_BIAS><<<384 + B3, 256, GEMM_SMEM_PIPE>>>(
        12, 384, px, W_in, pqkv, 3*EE, EE, b_in, nullptr,
        0, 0, nullptr, nullptr, nullptr, 0, 64, nullptr,
        0, 0, nullptr, nullptr, nullptr, 0, 64, nullptr,
        p, g_eln, b_eln, W_e, b_e, B1 + B2);

    // attention (needs g_bias complete)
    k_attnH<<<dim3(LL/64, BB*HH), 128, ATTN_SMEM>>>();
    k_gemmH<EPI_GATE_RES><<<dim3(4, 32), 256, GEMM_SMEM_PIPE>>>(
        po, W_out, ph1, EE, EE, b_out, pm, 2*EE, h);

    // MLP branch
    k_xmod<<<NROWS/4, 256>>>(ph1, 3*EE, 4*EE, px);
    k_gemmH<EPI_SILU><<<dim3(8, 32), 256, GEMM_SMEM_PIPE>>>(
        px, W1, pt1, MM_, EE, b1, nullptr, 0, nullptr);
    k_gemmH<EPI_GATE_RES><<<dim3(4, 32), 256, GEMM_SMEM_PIPE>>>(
        pt1, W2, ph2, EE, MM_, b2, pm, 5*EE, ph1);

    // trailing conditioning LayerNorms, fused (GEMMs precomputed in fatA)
    k_dual_ln<<<NROWS/4, 256>>>(ph2, ptt, g_tem, bt_tem, pti, g_init, bt_init, out);
}

// round 17
// speedup vs baseline: 1.0605x; 1.0605x over previous
#include <cuda_runtime.h>
#include <cuda_bf16.h>
#include <math.h>
#include <stdint.h>

// ---- problem constants ----
#define BB 8
#define LL 512
#define EE 256
#define HH 8
#define HD 32
#define BD_ 64
#define TD_ 256
#define TE_ 128
#define ED_ 64
#define MM_ 512
#define NROWS (BB*LL)          // 4096 token rows

typedef unsigned long long u64;

// ---- packed fp32x2 helpers ----
__device__ __forceinline__ u64 pk2(float x, float y) {
    u64 r; asm("mov.b64 %0,{%1,%2};" : "=l"(r) : "f"(x), "f"(y)); return r;
}
__device__ __forceinline__ void fma2(u64& d, u64 a, u64 b) {
    asm("fma.rn.f32x2 %0,%1,%2,%0;" : "+l"(d) : "l"(a), "l"(b));
}
__device__ __forceinline__ void unpk2(u64 v, float& x, float& y) {
    asm("mov.b64 {%0,%1},%2;" : "=f"(x), "=f"(y) : "l"(v));
}

// ---- HMMA / cp.async helpers (baseline PTX; valid on compute_103) ----
__device__ __forceinline__ uint32_t smem_u32(const void* p) {
    uint32_t a;
    asm("{ .reg .u64 t; cvta.to.shared.u64 t, %1; cvt.u32.u64 %0, t; }" : "=r"(a) : "l"(p));
    return a;
}
__device__ __forceinline__ void ldsm4(uint32_t& r0, uint32_t& r1, uint32_t& r2, uint32_t& r3,
                                      uint32_t addr) {
    asm volatile("ldmatrix.sync.aligned.m8n8.x4.shared.b16 {%0,%1,%2,%3},[%4];"
                 : "=r"(r0), "=r"(r1), "=r"(r2), "=r"(r3) : "r"(addr));
}
__device__ __forceinline__ void mma16816(float* d, const uint32_t* a, const uint32_t* b) {
    asm volatile(
        "mma.sync.aligned.m16n8k16.row.col.f32.bf16.bf16.f32 "
        "{%0,%1,%2,%3},{%4,%5,%6,%7},{%8,%9},{%0,%1,%2,%3};"
        : "+f"(d[0]), "+f"(d[1]), "+f"(d[2]), "+f"(d[3])
        : "r"(a[0]), "r"(a[1]), "r"(a[2]), "r"(a[3]), "r"(b[0]), "r"(b[1]));
}
__device__ __forceinline__ void cpasync16(uint32_t smaddr, const void* g) {
    asm volatile("cp.async.cg.shared.global [%0], [%1], 16;" :: "r"(smaddr), "l"(g));
}
#define CP_COMMIT() asm volatile("cp.async.commit_group;" ::: "memory")
#define CP_WAIT0()  asm volatile("cp.async.wait_group 0;" ::: "memory")
#define CP_WAIT1()  asm volatile("cp.async.wait_group 1;" ::: "memory")

// split fp32 -> bf16 hi + bf16 lo (residual), packed as bf16x2 pairs
__device__ __forceinline__ void split4(float4 v, uint2& hi, uint2& lo) {
    __nv_bfloat162 h01 = __float22bfloat162_rn(make_float2(v.x, v.y));
    __nv_bfloat162 h23 = __float22bfloat162_rn(make_float2(v.z, v.w));
    float2 f01 = __bfloat1622float2(h01);
    float2 f23 = __bfloat1622float2(h23);
    __nv_bfloat162 l01 = __float22bfloat162_rn(make_float2(v.x - f01.x, v.y - f01.y));
    __nv_bfloat162 l23 = __float22bfloat162_rn(make_float2(v.z - f23.x, v.w - f23.y));
    hi.x = *(uint32_t*)&h01; hi.y = *(uint32_t*)&h23;
    lo.x = *(uint32_t*)&l01; lo.y = *(uint32_t*)&l23;
}
__device__ __forceinline__ void packsplit(float x, float y, uint32_t& hi, uint32_t& lo) {
    __nv_bfloat162 h = __float22bfloat162_rn(make_float2(x, y));
    float2 f = __bfloat1622float2(h);
    __nv_bfloat162 l = __float22bfloat162_rn(make_float2(x - f.x, y - f.y));
    hi = *(uint32_t*)&h; lo = *(uint32_t*)&l;
}

// ---- scratch ----
__device__ float g_u[NROWS*TD_];
__device__ float g_m[NROWS*6*EE];
__device__ float g_x[NROWS*EE];
__device__ __nv_bfloat16 g_bias[(size_t)BB*HH*LL*LL];   // bf16 bias (32 MB)
__device__ float g_qkv[NROWS*3*EE];
__device__ float g_o[NROWS*EE];
__device__ float g_h1[NROWS*EE];
__device__ float g_t1[NROWS*MM_];
__device__ float g_h2[NROWS*EE];
__device__ float g_tt[NROWS*EE];   // s_tem @ W_tem^T + b_tem
__device__ float g_ti[NROWS*EE];   // h_init @ W_init^T + b_init

#define EPI_BIAS     0
#define EPI_SILU     1
#define EPI_GATE_RES 2
#define EPI_ADD_SILU 4

// =====================================================================
// GEMM epilogue (shared)
// =====================================================================
template<int EPI>
__device__ __forceinline__ void gemm_epilogue(
    float acc[2][4][4], int bm, int bn, int wm, int wn, int lane,
    float* __restrict__ C, int Nd, const float* __restrict__ bias,
    const float* __restrict__ gate, int goff, const float* __restrict__ res)
{
    int g = lane >> 2, tig = lane & 3;
    #pragma unroll
    for (int mi = 0; mi < 2; mi++) {
        #pragma unroll
        for (int ni = 0; ni < 4; ni++) {
            int n0 = bn + wn + ni*8 + tig*2;
            float2 b2 = *(const float2*)&bias[n0];
            #pragma unroll
            for (int rh = 0; rh < 2; rh++) {
                int m = bm + wm + mi*16 + g + rh*8;
                float x0 = acc[mi][ni][rh*2 + 0] + b2.x;
                float x1 = acc[mi][ni][rh*2 + 1] + b2.y;
                if (EPI == EPI_SILU) {
                    x0 = x0 / (1.f + __expf(-x0));
                    x1 = x1 / (1.f + __expf(-x1));
                }
                if (EPI == EPI_GATE_RES) {
                    float2 g2 = *(const float2*)&gate[(size_t)m*(6*EE) + goff + n0];
                    float2 r2 = *(const float2*)&res[(size_t)m*Nd + n0];
                    x0 = x0*g2.x + r2.x;
                    x1 = x1*g2.y + r2.y;
                }
                if (EPI == EPI_ADD_SILU) {
                    float2 r2 = *(const float2*)&res[(size_t)m*Nd + n0];
                    x0 += r2.x; x1 += r2.y;
                    x0 = x0 / (1.f + __expf(-x0));
                    x1 = x1 / (1.f + __expf(-x1));
                }
                *(float2*)&C[(size_t)m*Nd + n0] = make_float2(x0, x1);
            }
        }
    }
}

// =====================================================================
// cp.async-pipelined HMMA GEMM body (96KB)
// =====================================================================
#define OFF_AHI 0
#define OFF_ALO 16384
#define OFF_BHI 32768
#define OFF_BLO 40960
#define OFF_F32A 49152
#define OFF_F32B (49152 + 32768)
#define GEMM_SMEM_PIPE (49152 + 49152)

template<int EPI>
__device__ __forceinline__ void hmma_gemm_pipe(
    char* sm, int bm, int bn,
    const float* __restrict__ A, const float* __restrict__ B, float* __restrict__ C,
    int Nd, int Kd,
    const float* __restrict__ bias,
    const float* __restrict__ gate, int goff,
    const float* __restrict__ res)
{
    uint32_t sb = smem_u32(sm);
    int tid = threadIdx.x, wid = tid >> 5, lane = tid & 31;
    int wm = (wid & 3)*32, wn = (wid >> 2)*32;

    float acc[2][4][4];
    #pragma unroll
    for (int mi = 0; mi < 2; mi++)
        #pragma unroll
        for (int ni = 0; ni < 4; ni++)
            #pragma unroll
            for (int c = 0; c < 4; c++) acc[mi][ni][c] = 0.f;

    int arow = (lane & 15), acol = (lane >> 4);
    int brow = (lane & 7) + ((lane >> 4) << 3), bcol = (lane >> 3) & 1;

    int nch = Kd >> 6;
    {
        const float* Ab = A + (size_t)bm*Kd;
        const float* Bb = B + (size_t)bn*Kd;
        #pragma unroll
        for (int i = 0; i < 8; i++) {
            int idx = tid + i*256;
            int r = idx >> 4, c4 = idx & 15;
            cpasync16(sb + OFF_F32A + idx*16, Ab + (size_t)r*Kd + c4*4);
        }
        #pragma unroll
        for (int i = 0; i < 4; i++) {
            int idx = tid + i*256;
            int r = idx >> 4, c4 = idx & 15;
            cpasync16(sb + OFF_F32B + idx*16, Bb + (size_t)r*Kd + c4*4);
        }
        CP_COMMIT();
    }

    for (int ch = 0; ch < nch; ch++) {
        CP_WAIT0();
        __syncthreads();
        #pragma unroll
        for (int i = 0; i < 8; i++) {
            int idx = tid + i*256;
            int r = idx >> 4, c4 = idx & 15;
            float4 v = *(const float4*)(sm + OFF_F32A + idx*16);
            uint2 hi, lo; split4(v, hi, lo);
            uint32_t off = (uint32_t)(r*128 + c4*8);
            uint32_t sw = off ^ (((uint32_t)(r & 7)) << 4);
            *(uint2*)(sm + OFF_AHI + sw) = hi;
            *(uint2*)(sm + OFF_ALO + sw) = lo;
        }
        #pragma unroll
        for (int i = 0; i < 4; i++) {
            int idx = tid + i*256;
            int r = idx >> 4, c4 = idx & 15;
            float4 v = *(const float4*)(sm + OFF_F32B + idx*16);
            uint2 hi, lo; split4(v, hi, lo);
            uint32_t off = (uint32_t)(r*128 + c4*8);
            uint32_t sw = off ^ (((uint32_t)(r & 7)) << 4);
            *(uint2*)(sm + OFF_BHI + sw) = hi;
            *(uint2*)(sm + OFF_BLO + sw) = lo;
        }
        __syncthreads();

        if (ch + 1 < nch) {
            const float* Ab = A + (size_t)bm*Kd + (ch + 1)*64;
            const float* Bb = B + (size_t)bn*Kd + (ch + 1)*64;
            #pragma unroll
            for (int i = 0; i < 8; i++) {
                int idx = tid + i*256;
                int r = idx >> 4, c4 = idx & 15;
                cpasync16(sb + OFF_F32A + idx*16, Ab + (size_t)r*Kd + c4*4);
            }
            #pragma unroll
            for (int i = 0; i < 4; i++) {
                int idx = tid + i*256;
                int r = idx >> 4, c4 = idx & 15;
                cpasync16(sb + OFF_F32B + idx*16, Bb + (size_t)r*Kd + c4*4);
            }
            CP_COMMIT();
        }

        #pragma unroll
        for (int ks = 0; ks < 4; ks++) {
            uint32_t ah[2][4], al[2][4], bh[2][4], bl[2][4];
            #pragma unroll
            for (int mi = 0; mi < 2; mi++) {
                int row = wm + mi*16 + arow;
                uint32_t off = (uint32_t)(row*128 + (ks*2 + acol)*16);
                uint32_t sw = off ^ (((uint32_t)(row & 7)) << 4);
                ldsm4(ah[mi][0], ah[mi][1], ah[mi][2], ah[mi][3], sb + OFF_AHI + sw);
                ldsm4(al[mi][0], al[mi][1], al[mi][2], al[mi][3], sb + OFF_ALO + sw);
            }
            #pragma unroll
            for (int nh = 0; nh < 2; nh++) {
                int row = wn + nh*16 + brow;
                uint32_t off = (uint32_t)(row*128 + (ks*2 + bcol)*16);
                uint32_t sw = off ^ (((uint32_t)(row & 7)) << 4);
                ldsm4(bh[nh][0], bh[nh][1], bh[nh][2], bh[nh][3], sb + OFF_BHI + sw);
                ldsm4(bl[nh][0], bl[nh][1], bl[nh][2], bl[nh][3], sb + OFF_BLO + sw);
            }
            #pragma unroll
            for (int mi = 0; mi < 2; mi++)
                #pragma unroll
                for (int ni = 0; ni < 4; ni++) {
                    const uint32_t* bph = &bh[ni >> 1][(ni & 1)*2];
                    const uint32_t* bpl = &bl[ni >> 1][(ni & 1)*2];
                    mma16816(acc[mi][ni], ah[mi], bph);
                    mma16816(acc[mi][ni], ah[mi], bpl);
                    mma16816(acc[mi][ni], al[mi], bph);
                }
        }
    }
    gemm_epilogue<EPI>(acc, bm, bn, wm, wn, lane, C, Nd, bias, gate, goff, res);
}

template<int EPI>
__global__ void __launch_bounds__(256) k_gemmH(
    const float* __restrict__ A, const float* __restrict__ B, float* __restrict__ C,
    int Nd, int Kd,
    const float* __restrict__ bias,
    const float* __restrict__ gate, int goff,
    const float* __restrict__ res)
{
    extern __shared__ char smh[];
    hmma_gemm_pipe<EPI>(smh, blockIdx.y*128, blockIdx.x*64, A, B, C, Nd, Kd, bias, gate, goff, res);
}

// cond1 + Winit + Wtem in one launch (3 block ranges, all 128 blocks)
__global__ void __launch_bounds__(256) k_condgemms(
    const float* __restrict__ s_a, const float* __restrict__ W_bp, float* __restrict__ u,
    const float* __restrict__ b_bp, const float* __restrict__ s_t,
    const float* __restrict__ h_init, const float* __restrict__ W_init, float* __restrict__ ti,
    const float* __restrict__ b_init,
    const float* __restrict__ s_tem, const float* __restrict__ W_tem, float* __restrict__ tt,
    const float* __restrict__ b_tem)
{
    extern __shared__ char smc[];
    int bid = blockIdx.x;
    if (bid < 128) {
        hmma_gemm_pipe<EPI_ADD_SILU>(smc, (bid/4)*128, (bid & 3)*64,
                                     s_a, W_bp, u, TD_, BD_, b_bp, nullptr, 0, s_t);
    } else if (bid < 256) {
        int b2 = bid - 128;
        hmma_gemm_pipe<EPI_BIAS>(smc, (b2/4)*128, (b2 & 3)*64,
                                 h_init, W_init, ti, EE, EE, b_init, nullptr, 0, nullptr);
    } else {
        int b3 = bid - 256;
        hmma_gemm_pipe<EPI_BIAS>(smc, (b3/4)*128, (b3 & 3)*64,
                                 s_tem, W_tem, tt, EE, TE_, b_tem, nullptr, 0, nullptr);
    }
}

// =====================================================================
// bias body — cp.async double-buffered; bf16 output
// =====================================================================
#define FAT_SMEM ((2*128*64 + 512 + 16)*4)
__device__ __forceinline__ void bias_body(
        float* sm, int blk,
        const float* __restrict__ p, const float* __restrict__ g_eln,
        const float* __restrict__ b_eln, const float* __restrict__ W_e,
        const float* __restrict__ b_e)
{
    float* sW   = sm + 2*128*64;
    float* scs  = sW + 512;
    float* sct  = scs + 8;
    int tid = threadIdx.x;
    uint32_t sb = smem_u32(sm);

    for (int i = tid; i < 512; i += 256) sW[i] = g_eln[i & 63]*W_e[i];
    if (tid < 8) {
        float ct = 0.f;
        for (int k = 0; k < 64; k++) ct += b_eln[k]*W_e[tid*64 + k];
        sct[tid] = ct + b_e[tid];
    }
    __syncthreads();
    if (tid < 8) {
        float cs = 0.f;
        for (int k = 0; k < 64; k++) cs += sW[tid*64 + k];
        scs[tid] = cs;
    }

    int b = blk >> 9, l = blk & 511;
    const char* src = (const char*)(p + (size_t)blk*512*64);
    u64 one2 = pk2(1.f, 1.f);

    #pragma unroll
    for (int j = 0; j < 8; j++) {
        int idx = j*256 + tid;
        int r = idx >> 4, c = idx & 15;
        cpasync16(sb + (uint32_t)((r*64 + ((c ^ (r & 15)) << 2))*4), src + (size_t)idx*16);
    }
    CP_COMMIT();

    for (int ch = 0; ch < 4; ch++) {
        if (ch < 3) {
            uint32_t dstb = sb + (uint32_t)(((ch + 1) & 1)*32768);
            const char* s2 = src + (size_t)(ch + 1)*128*64*4;
            #pragma unroll
            for (int j = 0; j < 8; j++) {
                int idx = j*256 + tid;
                int r = idx >> 4, c = idx & 15;
                cpasync16(dstb + (uint32_t)((r*64 + ((c ^ (r & 15)) << 2))*4), s2 + (size_t)idx*16);
            }
            CP_COMMIT();
            CP_WAIT1();
        } else {
            CP_WAIT0();
        }
        __syncthreads();

        if (tid < 128) {
            const float* base = sm + (ch & 1)*8192 + tid*64;
            int swz = tid & 15;
            u64 P2[8] = {};
            u64 s2v = 0, q2 = 0;
            #pragma unroll
            for (int c = 0; c < 16; c++) {
                float4 a4 = *(const float4*)&base[(c ^ swz) << 2];
                u64 a01 = ((const u64*)&a4)[0];
                u64 a23 = ((const u64*)&a4)[1];
                fma2(s2v, a01, one2); fma2(s2v, a23, one2);
                fma2(q2, a01, a01);   fma2(q2, a23, a23);
                #pragma unroll
                for (int hh = 0; hh < 8; hh++) {
                    float4 w4 = *(const float4*)&sW[hh*64 + c*4];
                    fma2(P2[hh], a01, ((const u64*)&w4)[0]);
                    fma2(P2[hh], a23, ((const u64*)&w4)[1]);
                }
            }
            float sx, sy, qx, qy;
            unpk2(s2v, sx, sy); unpk2(q2, qx, qy);
            float s = sx + sy, q = qx + qy;
            float mu = s*(1.f/64.f);
            float var = q*(1.f/64.f) - mu*mu;
            float rstd = rsqrtf(var + 1e-5f);
            int m = ch*128 + tid;
            #pragma unroll
            for (int hh = 0; hh < 8; hh++) {
                float px, py;
                unpk2(P2[hh], px, py);
                float o = rstd*((px + py) - mu*scs[hh]) + sct[hh];
                g_bias[(((size_t)b*HH + hh)*LL + l)*LL + m] = __float2bfloat16_rn(o);
            }
        }
        __syncthreads();
    }
}

__global__ void __launch_bounds__(256) k_biasOnly(
        const float* __restrict__ p, const float* __restrict__ g_eln,
        const float* __restrict__ b_eln, const float* __restrict__ W_e,
        const float* __restrict__ b_e)
{
    extern __shared__ float smb[];
    bias_body(smb, blockIdx.x, p, g_eln, b_eln, W_e, b_e);
}

// =====================================================================
// k_xmod / k_dual_ln — float4, 4 rows per 256-thread block
// =====================================================================
__global__ void k_xmod(const float* __restrict__ src, int sh_off, int sc_off,
                       float* __restrict__ dst)
{
    int tid = threadIdx.x;
    int rl = tid >> 6, sub = tid & 63;
    int row = blockIdx.x*4 + rl;
    size_t base = (size_t)row*EE + sub*4;
    float4 v = *(const float4*)&src[base];
    float a = v.x + v.y + v.z + v.w;
    float b = v.x*v.x + v.y*v.y + v.z*v.z + v.w*v.w;
    #pragma unroll
    for (int o = 16; o > 0; o >>= 1) {
        a += __shfl_xor_sync(0xffffffffu, a, o);
        b += __shfl_xor_sync(0xffffffffu, b, o);
    }
    __shared__ float s1[8], s2[8];
    int wid = tid >> 5;
    if ((tid & 31) == 0) { s1[wid] = a; s2[wid] = b; }
    __syncthreads();
    float suma = s1[rl*2] + s1[rl*2 + 1];
    float sumb = s2[rl*2] + s2[rl*2 + 1];
    float mu = suma*(1.f/EE);
    float var = sumb*(1.f/EE) - mu*mu;
    float rstd = rsqrtf(var + 1e-5f);
    const float* mrow = g_m + (size_t)row*(6*EE);
    float4 sc4 = *(const float4*)&mrow[sc_off + sub*4];
    float4 sh4 = *(const float4*)&mrow[sh_off + sub*4];
    float4 o4;
    o4.x = (v.x - mu)*rstd*(1.f + sc4.x) + sh4.x;
    o4.y = (v.y - mu)*rstd*(1.f + sc4.y) + sh4.y;
    o4.z = (v.z - mu)*rstd*(1.f + sc4.z) + sh4.z;
    o4.w = (v.w - mu)*rstd*(1.f + sc4.w) + sh4.w;
    *(float4*)&dst[base] = o4;
}

__global__ void k_dual_ln(const float* __restrict__ a_, const float* __restrict__ b_,
                          const float* __restrict__ g1, const float* __restrict__ bt1,
                          const float* __restrict__ c_,
                          const float* __restrict__ g2, const float* __restrict__ bt2,
                          float* __restrict__ dst)
{
    int tid = threadIdx.x;
    int rl = tid >> 6, sub = tid & 63;
    int row = blockIdx.x*4 + rl;
    size_t base = (size_t)row*EE + sub*4;
    __shared__ float s1[8], s2[8];
    int wid = tid >> 5;

    float4 va = *(const float4*)&a_[base];
    float4 vb = *(const float4*)&b_[base];
    float4 v;
    v.x = va.x + vb.x; v.y = va.y + vb.y; v.z = va.z + vb.z; v.w = va.w + vb.w;
    float a = v.x + v.y + v.z + v.w;
    float b = v.x*v.x + v.y*v.y + v.z*v.z + v.w*v.w;
    #pragma unroll
    for (int o = 16; o > 0; o >>= 1) {
        a += __shfl_xor_sync(0xffffffffu, a, o);
        b += __shfl_xor_sync(0xffffffffu, b, o);
    }
    if ((tid & 31) == 0) { s1[wid] = a; s2[wid] = b; }
    __syncthreads();
    float mu = (s1[rl*2] + s1[rl*2+1])*(1.f/EE);
    float var = (s2[rl*2] + s2[rl*2+1])*(1.f/EE) - mu*mu;
    float rstd = rsqrtf(var + 1e-5f);
    float4 gg = *(const float4*)&g1[sub*4];
    float4 bb = *(const float4*)&bt1[sub*4];
    float4 x1;
    x1.x = (v.x - mu)*rstd*gg.x + bb.x;
    x1.y = (v.y - mu)*rstd*gg.y + bb.y;
    x1.z = (v.z - mu)*rstd*gg.z + bb.z;
    x1.w = (v.w - mu)*rstd*gg.w + bb.w;

    float4 vc = *(const float4*)&c_[base];
    float4 v2;
    v2.x = x1.x + vc.x; v2.y = x1.y + vc.y; v2.z = x1.z + vc.z; v2.w = x1.w + vc.w;
    a = v2.x + v2.y + v2.z + v2.w;
    b = v2.x*v2.x + v2.y*v2.y + v2.z*v2.z + v2.w*v2.w;
    #pragma unroll
    for (int o = 16; o > 0; o >>= 1) {
        a += __shfl_xor_sync(0xffffffffu, a, o);
        b += __shfl_xor_sync(0xffffffffu, b, o);
    }
    __syncthreads();    // s1/s2 reuse
    if ((tid & 31) == 0) { s1[wid] = a; s2[wid] = b; }
    __syncthreads();
    mu = (s1[rl*2] + s1[rl*2+1])*(1.f/EE);
    var = (s2[rl*2] + s2[rl*2+1])*(1.f/EE) - mu*mu;
    rstd = rsqrtf(var + 1e-5f);
    gg = *(const float4*)&g2[sub*4];
    bb = *(const float4*)&bt2[sub*4];
    float4 o4;
    o4.x = (v2.x - mu)*rstd*gg.x + bb.x;
    o4.y = (v2.y - mu)*rstd*gg.y + bb.y;
    o4.z = (v2.z - mu)*rstd*gg.z + bb.z;
    o4.w = (v2.w - mu)*rstd*gg.w + bb.w;
    *(float4*)&dst[base] = o4;
}

// =====================================================================
// k_attnH — HMMA flash attention + cp.async bf16-bias prefetch
// dynamic smem: Q 8K | K 8K | V 16K | bias 2x8K  = 48KB
// =====================================================================
#define AOFF_QH 0
#define AOFF_QL 4096
#define AOFF_KH 8192
#define AOFF_KL 12288
#define AOFF_VH 16384
#define AOFF_VL 24576
#define AOFF_B  32768
#define ATTN_SMEM 49152

__global__ void __launch_bounds__(128) k_attnH()
{
    extern __shared__ char sma[];
    char* sQh = sma + AOFF_QH;  char* sQl = sma + AOFF_QL;
    char* sKh = sma + AOFF_KH;  char* sKl = sma + AOFF_KL;
    char* sVh = sma + AOFF_VH;  char* sVl = sma + AOFF_VL;
    uint32_t sb = smem_u32(sma);

    int tid = threadIdx.x, lane = tid & 31, wid = tid >> 5;
    int bh = blockIdx.y;
    int b = bh >> 3, h = bh & 7;
    int l0 = blockIdx.x*64;
    int wm = wid*16;
    int g = lane >> 2, tig = lane & 3;

    // ---- stage Q (split bf16) ----
    #pragma unroll
    for (int i = 0; i < 4; i++) {
        int idx = tid + i*128;
        int r = idx >> 3, c4 = idx & 7;
        float4 v = *(const float4*)(g_qkv + (size_t)(b*LL + l0 + r)*768 + h*HD + c4*4);
        uint2 hi, lo; split4(v, hi, lo);
        int chunk = c4 >> 1, half = c4 & 1;
        int cs = chunk ^ ((r >> 1) & 3);
        int addr = r*64 + cs*16 + half*8;
        *(uint2*)(sQh + addr) = hi;
        *(uint2*)(sQl + addr) = lo;
    }
    // ---- prefetch bias chunk 0 (bf16; row = 1024B, chunk = 128B) ----
    const char* bsrc = (const char*)(g_bias + (((size_t)(b*HH + h)*LL + l0))*LL);
    #pragma unroll
    for (int j = 0; j < 4; j++) {
        int idx = j*128 + tid;
        int r = idx >> 3, cgr = idx & 7;
        cpasync16(sb + AOFF_B + (uint32_t)(r*128 + ((cgr ^ (r & 7)) << 4)),
                  bsrc + (size_t)r*1024 + cgr*16);
    }
    CP_COMMIT();
    __syncthreads();

    // ---- load Q fragments ----
    uint32_t qh[2][4], ql[2][4];
    {
        int arow = lane & 15, acol = lane >> 4;
        int row = wm + arow;
        #pragma unroll
        for (int kt = 0; kt < 2; kt++) {
            int c = kt*2 + acol;
            int cs = c ^ ((row >> 1) & 3);
            uint32_t off = (uint32_t)(row*64 + cs*16);
            ldsm4(qh[kt][0], qh[kt][1], qh[kt][2], qh[kt][3], sb + AOFF_QH + off);
            ldsm4(ql[kt][0], ql[kt][1], ql[kt][2], ql[kt][3], sb + AOFF_QL + off);
        }
    }

    float of[4][4];
    #pragma unroll
    for (int nt = 0; nt < 4; nt++)
        #pragma unroll
        for (int c = 0; c < 4; c++) of[nt][c] = 0.f;
    float m_run[2] = {-1e30f, -1e30f};
    float l_run[2] = {0.f, 0.f};

    int brow = (lane & 7) + ((lane >> 4) << 3);
    int bcol = (lane >> 3) & 1;
    const float sc = 0.17677669529663687f;

    for (int ch = 0; ch < 8; ch++) {
        int m0 = ch*64;
        __syncthreads();   // K/V buffer reuse; bias[ch-1] reads done
        // ---- stage K ----
        #pragma unroll
        for (int i = 0; i < 4; i++) {
            int idx = tid + i*128;
            int r = idx >> 3, c4 = idx & 7;
            float4 v = *(const float4*)(g_qkv + (size_t)(b*LL + m0 + r)*768 + 256 + h*HD + c4*4);
            uint2 hi, lo; split4(v, hi, lo);
            int chunk = c4 >> 1, half = c4 & 1;
            int cs = chunk ^ ((r >> 1) & 3);
            int addr = r*64 + cs*16 + half*8;
            *(uint2*)(sKh + addr) = hi;
            *(uint2*)(sKl + addr) = lo;
        }
        // ---- stage V transposed ----
        #pragma unroll
        for (int i = 0; i < 4; i++) {
            int idx = tid + i*128;
            int m = idx >> 3, c4 = idx & 7;
            float4 v = *(const float4*)(g_qkv + (size_t)(b*LL + m0 + m)*768 + 512 + h*HD + c4*4);
            float vf[4] = {v.x, v.y, v.z, v.w};
            #pragma unroll
            for (int j = 0; j < 4; j++) {
                int hd = c4*4 + j;
                __nv_bfloat16 hb = __float2bfloat16_rn(vf[j]);
                __nv_bfloat16 lb = __float2bfloat16_rn(vf[j] - __bfloat162float(hb));
                int cs = (m >> 3) ^ (hd & 7);
                int addr = hd*128 + cs*16 + (m & 7)*2;
                *(__nv_bfloat16*)(sVh + addr) = hb;
                *(__nv_bfloat16*)(sVl + addr) = lb;
            }
        }
        // ---- prefetch bias chunk ch+1 (overlaps S mma) ----
        if (ch < 7) {
            uint32_t dstb = sb + AOFF_B + (uint32_t)(((ch + 1) & 1)*8192);
            const char* b2 = bsrc + (size_t)(ch + 1)*128;   // next 64 m = 128 bytes
            #pragma unroll
            for (int j = 0; j < 4; j++) {
                int idx = j*128 + tid;
                int r = idx >> 3, cgr = idx & 7;
                cpasync16(dstb + (uint32_t)(r*128 + ((cgr ^ (r & 7)) << 4)),
                          b2 + (size_t)r*1024 + cgr*16);
            }
            CP_COMMIT();
        }
        __syncthreads();   // K/V visible

        // ---- S = Q K^T ----
        float s[8][4];
        #pragma unroll
        for (int nt = 0; nt < 8; nt++)
            #pragma unroll
            for (int c = 0; c < 4; c++) s[nt][c] = 0.f;
        #pragma unroll
        for (int ng = 0; ng < 4; ng++) {
            int row = ng*16 + brow;
            #pragma unroll
            for (int kt = 0; kt < 2; kt++) {
                int c = kt*2 + bcol;
                int cs = c ^ ((row >> 1) & 3);
                uint32_t off = (uint32_t)(row*64 + cs*16);
                uint32_t kh[4], kl[4];
                ldsm4(kh[0], kh[1], kh[2], kh[3], sb + AOFF_KH + off);
                ldsm4(kl[0], kl[1], kl[2], kl[3], sb + AOFF_KL + off);
                mma16816(s[2*ng],   qh[kt], &kh[0]);
                mma16816(s[2*ng+1], qh[kt], &kh[2]);
                mma16816(s[2*ng],   qh[kt], &kl[0]);
                mma16816(s[2*ng+1], qh[kt], &kl[2]);
                mma16816(s[2*ng],   ql[kt], &kh[0]);
                mma16816(s[2*ng+1], ql[kt], &kh[2]);
            }
        }

        // ---- wait bias[ch], then scale + bias (bf16 smem) ----
        if (ch < 7) { CP_WAIT1(); } else { CP_WAIT0(); }
        __syncthreads();
        {
            const char* bp = sma + AOFF_B + (ch & 1)*8192;
            int r0 = wm + g, r1 = wm + g + 8;
            #pragma unroll
            for (int nt = 0; nt < 8; nt++) {
                __nv_bfloat162 bb0 = *(const __nv_bfloat162*)(bp + r0*128 + ((nt ^ (r0 & 7)) << 4) + tig*4);
                __nv_bfloat162 bb1 = *(const __nv_bfloat162*)(bp + r1*128 + ((nt ^ (r1 & 7)) << 4) + tig*4);
                float2 b0 = __bfloat1622float2(bb0);
                float2 b1 = __bfloat1622float2(bb1);
                s[nt][0] = s[nt][0]*sc + b0.x;
                s[nt][1] = s[nt][1]*sc + b0.y;
                s[nt][2] = s[nt][2]*sc + b1.x;
                s[nt][3] = s[nt][3]*sc + b1.y;
            }
        }

        // ---- online softmax ----
        #pragma unroll
        for (int hf = 0; hf < 2; hf++) {
            int c0 = hf*2;
            float rm = -1e30f;
            #pragma unroll
            for (int nt = 0; nt < 8; nt++)
                rm = fmaxf(rm, fmaxf(s[nt][c0], s[nt][c0+1]));
            rm = fmaxf(rm, __shfl_xor_sync(0xffffffffu, rm, 1));
            rm = fmaxf(rm, __shfl_xor_sync(0xffffffffu, rm, 2));
            float mnew = fmaxf(m_run[hf], rm);
            float f = __expf(m_run[hf] - mnew);
            float rs = 0.f;
            #pragma unroll
            for (int nt = 0; nt < 8; nt++) {
                float p0 = __expf(s[nt][c0]   - mnew);
                float p1 = __expf(s[nt][c0+1] - mnew);
                s[nt][c0] = p0; s[nt][c0+1] = p1;
                rs += p0 + p1;
            }
            rs += __shfl_xor_sync(0xffffffffu, rs, 1);
            rs += __shfl_xor_sync(0xffffffffu, rs, 2);
            l_run[hf] = l_run[hf]*f + rs;
            m_run[hf] = mnew;
            #pragma unroll
            for (int nt = 0; nt < 4; nt++) { of[nt][c0] *= f; of[nt][c0+1] *= f; }
        }

        // ---- O += P V ----
        #pragma unroll
        for (int jp = 0; jp < 4; jp++) {
            uint32_t ah[4], al[4];
            packsplit(s[2*jp][0],   s[2*jp][1],   ah[0], al[0]);
            packsplit(s[2*jp][2],   s[2*jp][3],   ah[1], al[1]);
            packsplit(s[2*jp+1][0], s[2*jp+1][1], ah[2], al[2]);
            packsplit(s[2*jp+1][2], s[2*jp+1][3], ah[3], al[3]);
            uint32_t vh[2][4], vl[2][4];
            #pragma unroll
            for (int nh = 0; nh < 2; nh++) {
                int row = nh*16 + brow;
                int c = jp*2 + bcol;
                int cs = c ^ (row & 7);
                uint32_t off = (uint32_t)(row*128 + cs*16);
                ldsm4(vh[nh][0], vh[nh][1], vh[nh][2], vh[nh][3], sb + AOFF_VH + off);
                ldsm4(vl[nh][0], vl[nh][1], vl[nh][2], vl[nh][3], sb + AOFF_VL + off);
            }
            #pragma unroll
            for (int nt = 0; nt < 4; nt++) {
                const uint32_t* bph = &vh[nt >> 1][(nt & 1)*2];
                const uint32_t* bpl = &vl[nt >> 1][(nt & 1)*2];
                mma16816(of[nt], ah, bph);
                mma16816(of[nt], ah, bpl);
                mma16816(of[nt], al, bph);
            }
        }
    }

    float inv0 = 1.f/l_run[0], inv1 = 1.f/l_run[1];
    #pragma unroll
    for (int nt = 0; nt < 4; nt++) {
        int col = h*HD + nt*8 + tig*2;
        int r0 = b*LL + l0 + wm + g;
        *(float2*)&g_o[(size_t)r0*EE + col] =
            make_float2(of[nt][0]*inv0, of[nt][1]*inv0);
        *(float2*)&g_o[(size_t)(r0 + 8)*EE + col] =
            make_float2(of[nt][2]*inv1, of[nt][3]*inv1);
    }
}

// =====================================================================
// launch — fork: bias on DEFAULT stream, conditioning chain on
// HIGH-PRIORITY side stream (chain blocks preferentially scheduled as
// bias blocks retire => true co-residency this time).
// =====================================================================
extern "C" void kernel_launch(void* const* d_in, const int* in_sizes, int n_in,
                              void* d_out, int out_size)
{
    const float* h      = (const float*)d_in[0];
    const float* h_init = (const float*)d_in[1];
    const float* s_a    = (const float*)d_in[2];
    const float* s_t    = (const float*)d_in[3];
    const float* s_tem  = (const float*)d_in[4];
    const float* p      = (const float*)d_in[5];
    const float* W_bp   = (const float*)d_in[6];
    const float* b_bp   = (const float*)d_in[7];
    const float* W_ada  = (const float*)d_in[8];
    const float* b_ada  = (const float*)d_in[9];
    const float* g_eln  = (const float*)d_in[10];
    const float* b_eln  = (const float*)d_in[11];
    const float* W_e    = (const float*)d_in[12];
    const float* b_e    = (const float*)d_in[13];
    const float* W_in   = (const float*)d_in[14];
    const float* b_in   = (const float*)d_in[15];
    const float* W_out  = (const float*)d_in[16];
    const float* b_out  = (const float*)d_in[17];
    const float* W1     = (const float*)d_in[18];
    const float* b1     = (const float*)d_in[19];
    const float* W2     = (const float*)d_in[20];
    const float* b2     = (const float*)d_in[21];
    const float* W_tem  = (const float*)d_in[22];
    const float* b_tem  = (const float*)d_in[23];
    const float* g_tem  = (const float*)d_in[24];
    const float* bt_tem = (const float*)d_in[25];
    const float* W_init = (const float*)d_in[26];
    const float* b_init = (const float*)d_in[27];
    const float* g_init = (const float*)d_in[28];
    const float* bt_init= (const float*)d_in[29];
    float* out = (float*)d_out;

    float *pu, *pm, *px, *pqkv, *po, *ph1, *pt1, *ph2, *ptt, *pti;
    cudaGetSymbolAddress((void**)&pu,   g_u);
    cudaGetSymbolAddress((void**)&pm,   g_m);
    cudaGetSymbolAddress((void**)&px,   g_x);
    cudaGetSymbolAddress((void**)&pqkv, g_qkv);
    cudaGetSymbolAddress((void**)&po,   g_o);
    cudaGetSymbolAddress((void**)&ph1,  g_h1);
    cudaGetSymbolAddress((void**)&pt1,  g_t1);
    cudaGetSymbolAddress((void**)&ph2,  g_h2);
    cudaGetSymbolAddress((void**)&ptt,  g_tt);
    cudaGetSymbolAddress((void**)&pti,  g_ti);

    cudaFuncSetAttribute(k_biasOnly,  cudaFuncAttributeMaxDynamicSharedMemorySize, FAT_SMEM);
    cudaFuncSetAttribute(k_condgemms, cudaFuncAttributeMaxDynamicSharedMemorySize, GEMM_SMEM_PIPE);
    cudaFuncSetAttribute(k_gemmH<EPI_BIAS>,     cudaFuncAttributeMaxDynamicSharedMemorySize, GEMM_SMEM_PIPE);
    cudaFuncSetAttribute(k_gemmH<EPI_SILU>,     cudaFuncAttributeMaxDynamicSharedMemorySize, GEMM_SMEM_PIPE);
    cudaFuncSetAttribute(k_gemmH<EPI_GATE_RES>, cudaFuncAttributeMaxDynamicSharedMemorySize, GEMM_SMEM_PIPE);
    cudaFuncSetAttribute(k_attnH, cudaFuncAttributeMaxDynamicSharedMemorySize, ATTN_SMEM);

    // High-priority side stream for the conditioning chain; bias rides the
    // default stream. Fresh stream/events per call; not destroyed (capture-
    // forked streams must outlive EndCapture; no device memory involved).
    int plo, phi;
    cudaDeviceGetStreamPriorityRange(&plo, &phi);
    cudaStream_t s2;
    cudaStreamCreateWithPriority(&s2, cudaStreamNonBlocking, phi);
    cudaEvent_t evFork, evChain;
    cudaEventCreateWithFlags(&evFork, cudaEventDisableTiming);
    cudaEventCreateWithFlags(&evChain, cudaEventDisableTiming);

    cudaEventRecord(evFork, 0);
    cudaStreamWaitEvent(s2, evFork, 0);

    // chain on HIGH priority s2
    k_condgemms<<<384, 256, GEMM_SMEM_PIPE, s2>>>(
        s_a, W_bp, pu, b_bp, s_t,
        h_init, W_init, pti, b_init,
        s_tem, W_tem, ptt, b_tem);
    k_gemmH<EPI_BIAS><<<dim3(24, 32), 256, GEMM_SMEM_PIPE, s2>>>(
        pu, W_ada, pm, 6*EE, TD_, b_ada, nullptr, 0, nullptr);
    k_xmod<<<NROWS/4, 256, 0, s2>>>(h, 0, EE, px);
    k_gemmH<EPI_BIAS><<<dim3(12, 32), 256, GEMM_SMEM_PIPE, s2>>>(
        px, W_in, pqkv, 3*EE, EE, b_in, nullptr, 0, nullptr);
    cudaEventRecord(evChain, s2);

    // bias on default stream (overlaps chain; chain has scheduling priority)
    k_biasOnly<<<BB*LL, 256, FAT_SMEM>>>(p, g_eln, b_eln, W_e, b_e);

    // join: attention needs qkv (chain) + g_bias (default-stream order)
    cudaStreamWaitEvent(0, evChain, 0);
    k_attnH<<<dim3(LL/64, BB*HH), 128, ATTN_SMEM>>>();
    k_gemmH<EPI_GATE_RES><<<dim3(4, 32), 256, GEMM_SMEM_PIPE>>>(
        po, W_out, ph1, EE, EE, b_out, pm, 2*EE, h);

    // MLP branch
    k_xmod<<<NROWS/4, 256>>>(ph1, 3*EE, 4*EE, px);
    k_gemmH<EPI_SILU><<<dim3(8, 32), 256, GEMM_SMEM_PIPE>>>(
        px, W1, pt1, MM_, EE, b1, nullptr, 0, nullptr);
    k_gemmH<EPI_GATE_RES><<<dim3(4, 32), 256, GEMM_SMEM_PIPE>>>(
        pt1, W2, ph2, EE, MM_, b2, pm, 5*EE, ph1);

    // trailing conditioning LayerNorms, fused (GEMMs precomputed in condgemms)
    k_dual_ln<<<NROWS/4, 256>>>(ph2, ptt, g_tem, bt_tem, pti, g_init, bt_init, out);
}